// round 15
// baseline (speedup 1.0000x reference)
#include <cuda_runtime.h>
#include <cuda_fp16.h>
#include <math.h>
#include <stdint.h>

// ---------------- problem constants ----------------
#define N_MAXN    50000
#define NPAD      50048          // 391*128
#define MEM_DIM   100
#define RAW       64
#define TIN       20
#define D_MSG     292
#define KREAL     392
#define AK        416            // K padded to 13*32
#define KTOT      416
#define JB        400            // B rows: j = channel*4 + group

// ---------------- scratch ----------------
__device__ __half g_A[(size_t)NPAD * AK];
__device__ __half g_B[(size_t)JB * KTOT];
__device__ float  g_mem[(size_t)NPAD * MEM_DIM];

__device__ __forceinline__ uint32_t smem_u32(const void* p) {
    uint32_t a;
    asm("{ .reg .u64 t; cvta.to.shared.u64 t, %1; cvt.u32.u64 %0, t; }" : "=r"(a) : "l"(p));
    return a;
}
__device__ __forceinline__ void cp_async16(uint32_t dst, const void* src) {
    asm volatile("cp.async.cg.shared.global [%0], [%1], 16;" :: "r"(dst), "l"(src));
}
__device__ __forceinline__ void cp_commit() {
    asm volatile("cp.async.commit_group;" ::: "memory");
}
__device__ __forceinline__ void cp_wait1() {
    asm volatile("cp.async.wait_group 1;" ::: "memory");
}
__device__ __forceinline__ void cp_wait0() {
    asm volatile("cp.async.wait_group 0;" ::: "memory");
}
__device__ __forceinline__ void ldmx4(uint32_t* r, uint32_t addr) {
    asm volatile("ldmatrix.sync.aligned.m8n8.x4.shared.b16 {%0,%1,%2,%3}, [%4];"
        : "=r"(r[0]), "=r"(r[1]), "=r"(r[2]), "=r"(r[3]) : "r"(addr));
}
__device__ __forceinline__ void ldmx2(uint32_t* r, uint32_t addr) {
    asm volatile("ldmatrix.sync.aligned.m8n8.x2.shared.b16 {%0,%1}, [%2];"
        : "=r"(r[0]), "=r"(r[1]) : "r"(addr));
}
__device__ __forceinline__ void mma16816(float* d, const uint32_t* a, const uint32_t* b) {
    asm volatile(
        "mma.sync.aligned.m16n8k16.row.col.f32.f16.f16.f32 "
        "{%0,%1,%2,%3}, {%4,%5,%6,%7}, {%8,%9}, {%0,%1,%2,%3};"
        : "+f"(d[0]), "+f"(d[1]), "+f"(d[2]), "+f"(d[3])
        : "r"(a[0]), "r"(a[1]), "r"(a[2]), "r"(a[3]), "r"(b[0]), "r"(b[1]));
}

// ---------------------------------------------------------------------------
// Kernel 0: pack GRU weights -> g_B [400][416] fp16. (unchanged)
// ---------------------------------------------------------------------------
__global__ void buildB(const float* __restrict__ wih, const float* __restrict__ whh) {
    int idx = blockIdx.x * blockDim.x + threadIdx.x;
    if (idx >= JB * KTOT) return;
    int j = idx / KTOT, k = idx % KTOT;
    int c = j >> 2, g = j & 3;
    float v = 0.0f;
    if (k < D_MSG) {
        if (g == 0) v = wih[c * D_MSG + k];
        else if (g == 1) v = wih[(100 + c) * D_MSG + k];
        else if (g == 2) v = wih[(200 + c) * D_MSG + k];
    } else if (k < KREAL) {
        int m = k - D_MSG;
        if (g == 0) v = whh[c * MEM_DIM + m];
        else if (g == 1) v = whh[(100 + c) * MEM_DIM + m];
        else if (g == 3) v = whh[(200 + c) * MEM_DIM + m];
    }
    g_B[idx] = __float2half_rn(v);
}

// ---------------------------------------------------------------------------
// Kernel 1: warp-per-node msg MLP + layernorms. (unchanged from R12)
// ---------------------------------------------------------------------------
__global__ __launch_bounds__(256) void phase1(
    const int* __restrict__ n_id,
    const float* __restrict__ memory,
    const float* __restrict__ msgs,
    const float* __restrict__ w1, const float* __restrict__ b1,
    const float* __restrict__ w2, const float* __restrict__ b2,
    const float* __restrict__ lg, const float* __restrict__ lb,
    const float* __restrict__ lng, const float* __restrict__ lnb,
    int N)
{
    __shared__ float w1s[200], w2s[30];
    __shared__ float b1s[10], b2s[3], lgs[3], lbs[3];
    __shared__ float sv[8][296];

    int tid = threadIdx.x;
    int warp = tid >> 5, lane = tid & 31;

    if (tid < 200) w1s[tid] = w1[tid];
    else if (tid < 230) w2s[tid - 200] = w2[tid - 200];
    else if (tid < 240) b1s[tid - 230] = b1[tid - 230];
    else if (tid < 243) b2s[tid - 240] = b2[tid - 240];
    else if (tid < 246) lgs[tid - 243] = lg[tid - 243];
    else if (tid < 249) lbs[tid - 246] = lb[tid - 246];
    __syncthreads();

    int i = blockIdx.x * 8 + warp;
    size_t base = (size_t)i * AK;

    if (i >= N) {
        uint4 z = make_uint4(0, 0, 0, 0);
        uint4* dst = (uint4*)(g_A + base);
        if (lane < 26) { dst[lane] = z; dst[lane + 26] = z; }
        return;
    }
    int row = n_id[i];
    float* svw = sv[warp];

    const float* memrow = memory + (size_t)row * MEM_DIM;
#pragma unroll
    for (int c = lane; c < MEM_DIM; c += 32) svw[c] = memrow[c];

    float mr[2][TIN];
    const float4* m4 = (const float4*)(msgs + (size_t)row * (RAW * TIN));
#pragma unroll
    for (int rr = 0; rr < 2; rr++) {
        int r = 2 * lane + rr;
#pragma unroll
        for (int q = 0; q < 5; q++) {
            float4 v = __ldg(m4 + r * 5 + q);
            mr[rr][q * 4 + 0] = v.x; mr[rr][q * 4 + 1] = v.y;
            mr[rr][q * 4 + 2] = v.z; mr[rr][q * 4 + 3] = v.w;
        }
    }

    float h0[10], h1[10];
#pragma unroll
    for (int j = 0; j < 10; j++) {
        float s0 = b1s[j], s1 = b1s[j];
#pragma unroll
        for (int t = 0; t < TIN; t++) {
            float w = w1s[j * TIN + t];
            s0 = fmaf(mr[0][t], w, s0);
            s1 = fmaf(mr[1][t], w, s1);
        }
        h0[j] = 0.5f * s0 * (1.0f + erff(s0 * 0.7071067811865476f));
        h1[j] = 0.5f * s1 * (1.0f + erff(s1 * 0.7071067811865476f));
    }
#pragma unroll
    for (int rr = 0; rr < 2; rr++) {
        const float* h = rr ? h1 : h0;
        float y[3];
#pragma unroll
        for (int o = 0; o < 3; o++) {
            float s = b2s[o];
#pragma unroll
            for (int j = 0; j < 10; j++) s = fmaf(h[j], w2s[o * 10 + j], s);
            y[o] = s;
        }
        float mu = (y[0] + y[1] + y[2]) * (1.0f / 3.0f);
        float d0 = y[0] - mu, d1 = y[1] - mu, d2 = y[2] - mu;
        float var = (d0 * d0 + d1 * d1 + d2 * d2) * (1.0f / 3.0f);
        float rs = rsqrtf(var + 1e-5f);
        int r = 2 * lane + rr;
        svw[MEM_DIM + 3 * r + 0] = d0 * rs * lgs[0] + lbs[0];
        svw[MEM_DIM + 3 * r + 1] = d1 * rs * lgs[1] + lbs[1];
        svw[MEM_DIM + 3 * r + 2] = d2 * rs * lgs[2] + lbs[2];
    }
    __syncwarp();

    float s1 = 0.0f, s2 = 0.0f;
#pragma unroll
    for (int k = lane; k < D_MSG; k += 32) { float v = svw[k]; s1 += v; s2 += v * v; }
#pragma unroll
    for (int o = 16; o > 0; o >>= 1) {
        s1 += __shfl_xor_sync(0xFFFFFFFFu, s1, o);
        s2 += __shfl_xor_sync(0xFFFFFFFFu, s2, o);
    }
    float mu = s1 * (1.0f / 292.0f);
    float var = s2 * (1.0f / 292.0f) - mu * mu;
    float rs = rsqrtf(var + 1e-5f);

#pragma unroll
    for (int k = lane; k < D_MSG; k += 32) {
        float v = (svw[k] - mu) * rs * __ldg(lng + k) + __ldg(lnb + k);
        g_A[base + k] = __float2half_rn(v);
    }
#pragma unroll
    for (int c = lane; c < MEM_DIM; c += 32) {
        float v = svw[c];
        g_A[base + D_MSG + c] = __float2half_rn(v);
        g_mem[(size_t)i * MEM_DIM + c] = v;
    }
    if (lane < 24) g_A[base + KREAL + lane] = __float2half_rn(0.0f);
}

// ---------------------------------------------------------------------------
// Kernel 2: resident-A fp16 HMMA GEMM + fused GRU epilogue.
// One CTA per 128 rows. A tile loaded ONCE into smem (stride 424), then the
// CTA loops over all 5 column blocks (nb) with a 3-stage B pipeline.
// 512 threads, 16 warps (8 row x 2 col), warp tile 16x40.
// ---------------------------------------------------------------------------
#define BM 128
#define BN 80
#define BK 32
#define LDS 40
#define NKT 13
#define NB_BLK 5
#define NS (NKT * NB_BLK)           // 65
#define A_STRIDE 424                // halves; 16B-aligned rows, conflict-free
#define A_SM_H (BM * A_STRIDE)      // 54272 halves
#define B_H (BN * LDS)              // 3200 halves per stage
#define SMEM_GEMM ((A_SM_H + 3 * B_H) * 2)   // 127744 B

__global__ __launch_bounds__(512, 1) void gemm14(float* __restrict__ out, int N) {
    extern __shared__ __align__(16) uint16_t smx[];

    int tid = threadIdx.x;
    int lane = tid & 31, wid = tid >> 5;
    int wm = wid & 7, wn = wid >> 3;            // 8 x 2 warp grid
    int row0 = blockIdx.x * BM;

    const uint16_t* gA = (const uint16_t*)g_A;
    const uint16_t* gB = (const uint16_t*)g_B;
    uint32_t sbase = smem_u32(smx);

    // ---- load resident A tile: 128 rows x 52 chunks = 6656, 13/thread ----
#pragma unroll
    for (int q = 0; q < 13; q++) {
        int id = tid + q * 512;
        int r = id / 52, c = id % 52;
        cp_async16(sbase + (uint32_t)(r * A_STRIDE + c * 8) * 2,
                   gA + (size_t)(row0 + r) * AK + c * 8);
    }
    cp_commit();

    // ---- B loader: 320 chunks per stage, threads 0..319 ----
    bool bvalid = (tid < 320);
    int br = tid >> 2, bc = tid & 3;
    const uint16_t* bbase = gB + (size_t)br * KTOT + bc * 8;
    uint32_t bdst0 = (uint32_t)(A_SM_H + br * LDS + bc * 8) * 2;

    auto load_B = [&](int stage, int nb2, int kt2) {
        if (bvalid)
            cp_async16(sbase + bdst0 + (uint32_t)(stage * B_H) * 2,
                       bbase + (size_t)nb2 * 80 * KTOT + kt2 * BK);
        cp_commit();
    };

    load_B(0, 0, 0);
    load_B(1, 0, 1);

    int s = 0;
    for (int nb = 0; nb < NB_BLK; nb++) {
        float acc[5][4];
#pragma unroll
        for (int nf = 0; nf < 5; nf++)
#pragma unroll
            for (int q = 0; q < 4; q++) acc[nf][q] = 0.0f;

#pragma unroll
        for (int kt = 0; kt < NKT; kt++) {
            if (s < NS - 1) cp_wait1(); else cp_wait0();
            __syncthreads();
            if (s + 2 < NS) {
                int kt2 = kt + 2, nb2 = nb;
                if (kt2 >= NKT) { kt2 -= NKT; nb2++; }
                load_B((s + 2) % 3, nb2, kt2);
            }

            const uint16_t* As = smx;
            const uint16_t* Bs = smx + A_SM_H + (s % 3) * B_H;
#pragma unroll
            for (int ks = 0; ks < 2; ks++) {
                int ka = kt * BK + ks * 16;
                uint32_t a[4], b[5][2];
                {
                    int r = wm * 16 + (lane & 15);
                    int c = ka + (lane >> 4) * 8;
                    ldmx4(a, smem_u32(&As[r * A_STRIDE + c]));
                }
                int k0 = ks * 16;
#pragma unroll
                for (int pr = 0; pr < 2; pr++) {
                    int r = wn * 40 + pr * 16 + (lane & 7) + ((lane >> 4) << 3);
                    int c = k0 + ((lane >> 3) & 1) * 8;
                    uint32_t bb[4];
                    ldmx4(bb, smem_u32(&Bs[r * LDS + c]));
                    b[2 * pr][0] = bb[0]; b[2 * pr][1] = bb[1];
                    b[2 * pr + 1][0] = bb[2]; b[2 * pr + 1][1] = bb[3];
                }
                {
                    int r = wn * 40 + 32 + (lane & 7);
                    int c = k0 + ((lane >> 3) & 1) * 8;
                    ldmx2(b[4], smem_u32(&Bs[r * LDS + c]));
                }
#pragma unroll
                for (int nf = 0; nf < 5; nf++)
                    mma16816(acc[nf], a, b[nf]);
            }
            s++;
        }

        // ---- R12-style register-fused GRU epilogue for this column block ----
        int r0i = row0 + wm * 16 + (lane >> 2);
#pragma unroll
        for (int nf = 0; nf < 5; nf++) {
            float n0 = __shfl_xor_sync(0xFFFFFFFFu, acc[nf][0], 1);
            float n1 = __shfl_xor_sync(0xFFFFFFFFu, acc[nf][1], 1);
            float n2 = __shfl_xor_sync(0xFFFFFFFFu, acc[nf][2], 1);
            float n3 = __shfl_xor_sync(0xFFFFFFFFu, acc[nf][3], 1);
            if (!(lane & 1)) {
                int ch = nb * 20 + wn * 10 + nf * 2 + ((lane & 3) >> 1);
                if (ch < MEM_DIM) {
                    if (r0i < N) {
                        float rr = 1.0f / (1.0f + expf(-acc[nf][0]));
                        float zz = 1.0f / (1.0f + expf(-acc[nf][1]));
                        float nn = tanhf(fmaf(rr, n1, n0));
                        float m = g_mem[(size_t)r0i * MEM_DIM + ch];
                        out[(size_t)r0i * MEM_DIM + ch] = (1.0f - zz) * nn + zz * m;
                    }
                    int r1i = r0i + 8;
                    if (r1i < N) {
                        float rr = 1.0f / (1.0f + expf(-acc[nf][2]));
                        float zz = 1.0f / (1.0f + expf(-acc[nf][3]));
                        float nn = tanhf(fmaf(rr, n3, n2));
                        float m = g_mem[(size_t)r1i * MEM_DIM + ch];
                        out[(size_t)r1i * MEM_DIM + ch] = (1.0f - zz) * nn + zz * m;
                    }
                }
            }
        }
    }
}

// ---------------------------------------------------------------------------
extern "C" void kernel_launch(void* const* d_in, const int* in_sizes, int n_in,
                              void* d_out, int out_size) {
    const int*   n_id   = (const int*)d_in[0];
    const float* memory = (const float*)d_in[1];
    const float* msgs   = (const float*)d_in[2];
    const float* w1     = (const float*)d_in[3];
    const float* b1     = (const float*)d_in[4];
    const float* w2     = (const float*)d_in[5];
    const float* b2     = (const float*)d_in[6];
    const float* lg     = (const float*)d_in[7];
    const float* lb     = (const float*)d_in[8];
    const float* lng    = (const float*)d_in[9];
    const float* lnb    = (const float*)d_in[10];
    const float* wih    = (const float*)d_in[11];
    const float* whh    = (const float*)d_in[12];
    float* out = (float*)d_out;

    int N = in_sizes[0];
    if (N > N_MAXN) N = N_MAXN;

    cudaFuncSetAttribute(gemm14, cudaFuncAttributeMaxDynamicSharedMemorySize, SMEM_GEMM);

    buildB<<<(JB * KTOT + 255) / 256, 256>>>(wih, whh);
    phase1<<<NPAD / 8, 256>>>(n_id, memory, msgs, w1, b1, w2, b2, lg, lb, lng, lnb, N);
    gemm14<<<NPAD / BM, 512, SMEM_GEMM>>>(out, N);
}

// round 16
// speedup vs baseline: 1.1245x; 1.1245x over previous
#include <cuda_runtime.h>
#include <cuda_fp16.h>
#include <math.h>
#include <stdint.h>

// ---------------- problem constants ----------------
#define N_MAXN    50000
#define NPAD      50176          // 196*256, 6272*8
#define MEM_DIM   100
#define RAW       64
#define TIN       20
#define D_MSG     292
#define KREAL     392
#define AK        416            // K padded to 13*32
#define KTOT      416
#define JB        400            // B rows: j = channel*4 + group

// ---------------- scratch ----------------
__device__ __half g_A[(size_t)NPAD * AK];
__device__ __half g_B[(size_t)JB * KTOT];
__device__ float  g_mem[(size_t)NPAD * MEM_DIM];

__device__ __forceinline__ uint32_t smem_u32(const void* p) {
    uint32_t a;
    asm("{ .reg .u64 t; cvta.to.shared.u64 t, %1; cvt.u32.u64 %0, t; }" : "=r"(a) : "l"(p));
    return a;
}
__device__ __forceinline__ void cp_async16(uint32_t dst, const void* src) {
    asm volatile("cp.async.cg.shared.global [%0], [%1], 16;" :: "r"(dst), "l"(src));
}
__device__ __forceinline__ void cp_commit() {
    asm volatile("cp.async.commit_group;" ::: "memory");
}
__device__ __forceinline__ void cp_wait1() {
    asm volatile("cp.async.wait_group 1;" ::: "memory");
}
__device__ __forceinline__ void cp_wait0() {
    asm volatile("cp.async.wait_group 0;" ::: "memory");
}
__device__ __forceinline__ void ldmx4(uint32_t* r, uint32_t addr) {
    asm volatile("ldmatrix.sync.aligned.m8n8.x4.shared.b16 {%0,%1,%2,%3}, [%4];"
        : "=r"(r[0]), "=r"(r[1]), "=r"(r[2]), "=r"(r[3]) : "r"(addr));
}
__device__ __forceinline__ void ldmx2(uint32_t* r, uint32_t addr) {
    asm volatile("ldmatrix.sync.aligned.m8n8.x2.shared.b16 {%0,%1}, [%2];"
        : "=r"(r[0]), "=r"(r[1]) : "r"(addr));
}
__device__ __forceinline__ void mma16816(float* d, const uint32_t* a, const uint32_t* b) {
    asm volatile(
        "mma.sync.aligned.m16n8k16.row.col.f32.f16.f16.f32 "
        "{%0,%1,%2,%3}, {%4,%5,%6,%7}, {%8,%9}, {%0,%1,%2,%3};"
        : "+f"(d[0]), "+f"(d[1]), "+f"(d[2]), "+f"(d[3])
        : "r"(a[0]), "r"(a[1]), "r"(a[2]), "r"(a[3]), "r"(b[0]), "r"(b[1]));
}

// ---------------------------------------------------------------------------
// Kernel 0: pack GRU weights -> g_B [400][416] fp16. (unchanged)
// ---------------------------------------------------------------------------
__global__ void buildB(const float* __restrict__ wih, const float* __restrict__ whh) {
    int idx = blockIdx.x * blockDim.x + threadIdx.x;
    if (idx >= JB * KTOT) return;
    int j = idx / KTOT, k = idx % KTOT;
    int c = j >> 2, g = j & 3;
    float v = 0.0f;
    if (k < D_MSG) {
        if (g == 0) v = wih[c * D_MSG + k];
        else if (g == 1) v = wih[(100 + c) * D_MSG + k];
        else if (g == 2) v = wih[(200 + c) * D_MSG + k];
    } else if (k < KREAL) {
        int m = k - D_MSG;
        if (g == 0) v = whh[c * MEM_DIM + m];
        else if (g == 1) v = whh[(100 + c) * MEM_DIM + m];
        else if (g == 3) v = whh[(200 + c) * MEM_DIM + m];
    }
    g_B[idx] = __float2half_rn(v);
}

// ---------------------------------------------------------------------------
// Kernel 1: warp-per-node msg MLP + layernorms. (unchanged from R12)
// ---------------------------------------------------------------------------
__global__ __launch_bounds__(256) void phase1(
    const int* __restrict__ n_id,
    const float* __restrict__ memory,
    const float* __restrict__ msgs,
    const float* __restrict__ w1, const float* __restrict__ b1,
    const float* __restrict__ w2, const float* __restrict__ b2,
    const float* __restrict__ lg, const float* __restrict__ lb,
    const float* __restrict__ lng, const float* __restrict__ lnb,
    int N)
{
    __shared__ float w1s[200], w2s[30];
    __shared__ float b1s[10], b2s[3], lgs[3], lbs[3];
    __shared__ float sv[8][296];

    int tid = threadIdx.x;
    int warp = tid >> 5, lane = tid & 31;

    if (tid < 200) w1s[tid] = w1[tid];
    else if (tid < 230) w2s[tid - 200] = w2[tid - 200];
    else if (tid < 240) b1s[tid - 230] = b1[tid - 230];
    else if (tid < 243) b2s[tid - 240] = b2[tid - 240];
    else if (tid < 246) lgs[tid - 243] = lg[tid - 243];
    else if (tid < 249) lbs[tid - 246] = lb[tid - 246];
    __syncthreads();

    int i = blockIdx.x * 8 + warp;
    size_t base = (size_t)i * AK;

    if (i >= N) {
        uint4 z = make_uint4(0, 0, 0, 0);
        uint4* dst = (uint4*)(g_A + base);
        if (lane < 26) { dst[lane] = z; dst[lane + 26] = z; }
        return;
    }
    int row = n_id[i];
    float* svw = sv[warp];

    const float* memrow = memory + (size_t)row * MEM_DIM;
#pragma unroll
    for (int c = lane; c < MEM_DIM; c += 32) svw[c] = memrow[c];

    float mr[2][TIN];
    const float4* m4 = (const float4*)(msgs + (size_t)row * (RAW * TIN));
#pragma unroll
    for (int rr = 0; rr < 2; rr++) {
        int r = 2 * lane + rr;
#pragma unroll
        for (int q = 0; q < 5; q++) {
            float4 v = __ldg(m4 + r * 5 + q);
            mr[rr][q * 4 + 0] = v.x; mr[rr][q * 4 + 1] = v.y;
            mr[rr][q * 4 + 2] = v.z; mr[rr][q * 4 + 3] = v.w;
        }
    }

    float h0[10], h1[10];
#pragma unroll
    for (int j = 0; j < 10; j++) {
        float s0 = b1s[j], s1 = b1s[j];
#pragma unroll
        for (int t = 0; t < TIN; t++) {
            float w = w1s[j * TIN + t];
            s0 = fmaf(mr[0][t], w, s0);
            s1 = fmaf(mr[1][t], w, s1);
        }
        h0[j] = 0.5f * s0 * (1.0f + erff(s0 * 0.7071067811865476f));
        h1[j] = 0.5f * s1 * (1.0f + erff(s1 * 0.7071067811865476f));
    }
#pragma unroll
    for (int rr = 0; rr < 2; rr++) {
        const float* h = rr ? h1 : h0;
        float y[3];
#pragma unroll
        for (int o = 0; o < 3; o++) {
            float s = b2s[o];
#pragma unroll
            for (int j = 0; j < 10; j++) s = fmaf(h[j], w2s[o * 10 + j], s);
            y[o] = s;
        }
        float mu = (y[0] + y[1] + y[2]) * (1.0f / 3.0f);
        float d0 = y[0] - mu, d1 = y[1] - mu, d2 = y[2] - mu;
        float var = (d0 * d0 + d1 * d1 + d2 * d2) * (1.0f / 3.0f);
        float rs = rsqrtf(var + 1e-5f);
        int r = 2 * lane + rr;
        svw[MEM_DIM + 3 * r + 0] = d0 * rs * lgs[0] + lbs[0];
        svw[MEM_DIM + 3 * r + 1] = d1 * rs * lgs[1] + lbs[1];
        svw[MEM_DIM + 3 * r + 2] = d2 * rs * lgs[2] + lbs[2];
    }
    __syncwarp();

    float s1 = 0.0f, s2 = 0.0f;
#pragma unroll
    for (int k = lane; k < D_MSG; k += 32) { float v = svw[k]; s1 += v; s2 += v * v; }
#pragma unroll
    for (int o = 16; o > 0; o >>= 1) {
        s1 += __shfl_xor_sync(0xFFFFFFFFu, s1, o);
        s2 += __shfl_xor_sync(0xFFFFFFFFu, s2, o);
    }
    float mu = s1 * (1.0f / 292.0f);
    float var = s2 * (1.0f / 292.0f) - mu * mu;
    float rs = rsqrtf(var + 1e-5f);

#pragma unroll
    for (int k = lane; k < D_MSG; k += 32) {
        float v = (svw[k] - mu) * rs * __ldg(lng + k) + __ldg(lnb + k);
        g_A[base + k] = __float2half_rn(v);
    }
#pragma unroll
    for (int c = lane; c < MEM_DIM; c += 32) {
        float v = svw[c];
        g_A[base + D_MSG + c] = __float2half_rn(v);
        g_mem[(size_t)i * MEM_DIM + c] = v;
    }
    if (lane < 24) g_A[base + KREAL + lane] = __float2half_rn(0.0f);
}

// ---------------------------------------------------------------------------
// Kernel 2: fp16 HMMA GEMM + register-fused GRU epilogue.
// BM=256 BN=80 BK=32, 512 threads, 16 warps (8x2, warp tile 32x40).
// 3-stage cp.async pipeline, 2 CTA/SM preserved (80.6 KB smem).
// ---------------------------------------------------------------------------
#define BM 256
#define BN 80
#define BK 32
#define LDS 40
#define NKT (KTOT / BK)   // 13
#define A_H (BM * LDS)    // 10240 halves
#define B_H (BN * LDS)    // 3200 halves
#define STG_H (A_H + B_H) // 13440 halves = 26880 B
#define SMEM_GEMM (3 * STG_H * 2)   // 80640 B

__global__ __launch_bounds__(512, 2) void gemm16(float* __restrict__ out, int N) {
    extern __shared__ __align__(16) uint16_t smx[];

    int tid = threadIdx.x;
    int lane = tid & 31, wid = tid >> 5;
    int wm = wid & 7, wn = wid >> 3;            // 8 x 2 warp grid
    int row0 = blockIdx.y * BM;
    int colblk = blockIdx.x;                    // channels [colblk*20, +20)
    int col0 = colblk * BN;

    const uint16_t* gA = (const uint16_t*)g_A;
    const uint16_t* gB = (const uint16_t*)g_B;

    float acc[2][5][4];
#pragma unroll
    for (int mf = 0; mf < 2; mf++)
#pragma unroll
        for (int nf = 0; nf < 5; nf++)
#pragma unroll
            for (int q = 0; q < 4; q++) acc[mf][nf][q] = 0.0f;

    // ---- hoisted loader geometry: A 1024 chunks + B 320 = 1344, 3/thread ----
    const uint16_t* gsrc[3];
    uint32_t sdst[3];
    bool valid[3];
#pragma unroll
    for (int q = 0; q < 3; q++) {
        int id = tid + q * 512;
        valid[q] = (id < 1344);
        if (id < 1024) {
            int r = id >> 2, c = id & 3;
            gsrc[q] = gA + (size_t)(row0 + r) * AK + c * 8;
            sdst[q] = r * LDS + c * 8;
        } else if (id < 1344) {
            int id2 = id - 1024;
            int r = id2 >> 2, c = id2 & 3;
            gsrc[q] = gB + (size_t)(col0 + r) * KTOT + c * 8;
            sdst[q] = A_H + r * LDS + c * 8;
        } else {
            gsrc[q] = gB; sdst[q] = 0;
        }
    }
    uint32_t sbase = smem_u32(smx);

    auto load_stage = [&](int stage, int k0) {
        uint32_t soff = sbase + (uint32_t)(stage * STG_H) * 2;
#pragma unroll
        for (int q = 0; q < 3; q++) {
            if (!valid[q]) continue;
            cp_async16(soff + sdst[q] * 2, gsrc[q] + k0);
        }
        cp_commit();
    };

    load_stage(0, 0);
    load_stage(1, BK);

    for (int kt = 0; kt < NKT; kt++) {
        int buf = kt % 3;
        if (kt + 1 < NKT) cp_wait1(); else cp_wait0();
        __syncthreads();
        if (kt + 2 < NKT) load_stage((kt + 2) % 3, (kt + 2) * BK);

        uint16_t* As = smx + buf * STG_H;
        uint16_t* Bs = As + A_H;
#pragma unroll
        for (int ks = 0; ks < 2; ks++) {
            int k0 = ks * 16;
            uint32_t a[2][4], b[5][2];
#pragma unroll
            for (int mf = 0; mf < 2; mf++) {
                int r = wm * 32 + mf * 16 + (lane & 15);
                int c = k0 + (lane >> 4) * 8;
                ldmx4(a[mf], smem_u32(&As[r * LDS + c]));
            }
#pragma unroll
            for (int pr = 0; pr < 2; pr++) {
                int r = wn * 40 + pr * 16 + (lane & 7) + ((lane >> 4) << 3);
                int c = k0 + ((lane >> 3) & 1) * 8;
                uint32_t bb[4];
                ldmx4(bb, smem_u32(&Bs[r * LDS + c]));
                b[2 * pr][0] = bb[0]; b[2 * pr][1] = bb[1];
                b[2 * pr + 1][0] = bb[2]; b[2 * pr + 1][1] = bb[3];
            }
            {
                int r = wn * 40 + 32 + (lane & 7);
                int c = k0 + ((lane >> 3) & 1) * 8;
                ldmx2(b[4], smem_u32(&Bs[r * LDS + c]));
            }
#pragma unroll
            for (int mf = 0; mf < 2; mf++)
#pragma unroll
                for (int nf = 0; nf < 5; nf++)
                    mma16816(acc[mf][nf], a[mf], b[nf]);
        }
    }

    // Register-fused GRU epilogue (R12-proven form).
#pragma unroll
    for (int mf = 0; mf < 2; mf++) {
        int r0i = row0 + wm * 32 + mf * 16 + (lane >> 2);
#pragma unroll
        for (int nf = 0; nf < 5; nf++) {
            float n0 = __shfl_xor_sync(0xFFFFFFFFu, acc[mf][nf][0], 1);
            float n1 = __shfl_xor_sync(0xFFFFFFFFu, acc[mf][nf][1], 1);
            float n2 = __shfl_xor_sync(0xFFFFFFFFu, acc[mf][nf][2], 1);
            float n3 = __shfl_xor_sync(0xFFFFFFFFu, acc[mf][nf][3], 1);
            if (!(lane & 1)) {
                int ch = colblk * 20 + wn * 10 + nf * 2 + ((lane & 3) >> 1);
                if (ch < MEM_DIM) {
                    if (r0i < N) {
                        float rr = 1.0f / (1.0f + expf(-acc[mf][nf][0]));
                        float zz = 1.0f / (1.0f + expf(-acc[mf][nf][1]));
                        float nn = tanhf(fmaf(rr, n1, n0));
                        float m = g_mem[(size_t)r0i * MEM_DIM + ch];
                        out[(size_t)r0i * MEM_DIM + ch] = (1.0f - zz) * nn + zz * m;
                    }
                    int r1i = r0i + 8;
                    if (r1i < N) {
                        float rr = 1.0f / (1.0f + expf(-acc[mf][nf][2]));
                        float zz = 1.0f / (1.0f + expf(-acc[mf][nf][3]));
                        float nn = tanhf(fmaf(rr, n3, n2));
                        float m = g_mem[(size_t)r1i * MEM_DIM + ch];
                        out[(size_t)r1i * MEM_DIM + ch] = (1.0f - zz) * nn + zz * m;
                    }
                }
            }
        }
    }
}

// ---------------------------------------------------------------------------
extern "C" void kernel_launch(void* const* d_in, const int* in_sizes, int n_in,
                              void* d_out, int out_size) {
    const int*   n_id   = (const int*)d_in[0];
    const float* memory = (const float*)d_in[1];
    const float* msgs   = (const float*)d_in[2];
    const float* w1     = (const float*)d_in[3];
    const float* b1     = (const float*)d_in[4];
    const float* w2     = (const float*)d_in[5];
    const float* b2     = (const float*)d_in[6];
    const float* lg     = (const float*)d_in[7];
    const float* lb     = (const float*)d_in[8];
    const float* lng    = (const float*)d_in[9];
    const float* lnb    = (const float*)d_in[10];
    const float* wih    = (const float*)d_in[11];
    const float* whh    = (const float*)d_in[12];
    float* out = (float*)d_out;

    int N = in_sizes[0];
    if (N > N_MAXN) N = N_MAXN;

    cudaFuncSetAttribute(gemm16, cudaFuncAttributeMaxDynamicSharedMemorySize, SMEM_GEMM);

    buildB<<<(JB * KTOT + 255) / 256, 256>>>(wih, whh);
    phase1<<<NPAD / 8, 256>>>(n_id, memory, msgs, w1, b1, w2, b2, lg, lb, lng, lnb, N);
    dim3 grid(5, NPAD / BM);   // col-block fast -> A shared in L2
    gemm16<<<grid, 512, SMEM_GEMM>>>(out, N);
}

// round 17
// speedup vs baseline: 1.2313x; 1.0950x over previous
#include <cuda_runtime.h>
#include <cuda_fp16.h>
#include <math.h>
#include <stdint.h>

// ---------------- problem constants ----------------
#define N_MAXN    50000
#define NPAD      50048          // 391*128, 6256*8
#define MEM_DIM   100
#define RAW       64
#define TIN       20
#define D_MSG     292
#define KREAL     392
#define AK        416            // K padded to 13*32
#define KTOT      416
#define JB        400            // B rows: j = channel*4 + group

// ---------------- scratch ----------------
__device__ __half g_A[(size_t)NPAD * AK];
__device__ __half g_B[(size_t)JB * KTOT];
__device__ float  g_mem[(size_t)NPAD * MEM_DIM];

__device__ __forceinline__ uint32_t smem_u32(const void* p) {
    uint32_t a;
    asm("{ .reg .u64 t; cvta.to.shared.u64 t, %1; cvt.u32.u64 %0, t; }" : "=r"(a) : "l"(p));
    return a;
}
__device__ __forceinline__ void cp_async16(uint32_t dst, const void* src) {
    asm volatile("cp.async.cg.shared.global [%0], [%1], 16;" :: "r"(dst), "l"(src));
}
__device__ __forceinline__ void cp_commit() {
    asm volatile("cp.async.commit_group;" ::: "memory");
}
__device__ __forceinline__ void cp_wait1() {
    asm volatile("cp.async.wait_group 1;" ::: "memory");
}
__device__ __forceinline__ void cp_wait0() {
    asm volatile("cp.async.wait_group 0;" ::: "memory");
}
__device__ __forceinline__ void ldmx4(uint32_t* r, uint32_t addr) {
    asm volatile("ldmatrix.sync.aligned.m8n8.x4.shared.b16 {%0,%1,%2,%3}, [%4];"
        : "=r"(r[0]), "=r"(r[1]), "=r"(r[2]), "=r"(r[3]) : "r"(addr));
}
__device__ __forceinline__ void ldmx2(uint32_t* r, uint32_t addr) {
    asm volatile("ldmatrix.sync.aligned.m8n8.x2.shared.b16 {%0,%1}, [%2];"
        : "=r"(r[0]), "=r"(r[1]) : "r"(addr));
}
__device__ __forceinline__ void mma16816(float* d, const uint32_t* a, const uint32_t* b) {
    asm volatile(
        "mma.sync.aligned.m16n8k16.row.col.f32.f16.f16.f32 "
        "{%0,%1,%2,%3}, {%4,%5,%6,%7}, {%8,%9}, {%0,%1,%2,%3};"
        : "+f"(d[0]), "+f"(d[1]), "+f"(d[2]), "+f"(d[3])
        : "r"(a[0]), "r"(a[1]), "r"(a[2]), "r"(a[3]), "r"(b[0]), "r"(b[1]));
}

// ---------------------------------------------------------------------------
// Kernel 0: pack GRU weights -> g_B [400][416] fp16. (unchanged)
// ---------------------------------------------------------------------------
__global__ void buildB(const float* __restrict__ wih, const float* __restrict__ whh) {
    int idx = blockIdx.x * blockDim.x + threadIdx.x;
    if (idx >= JB * KTOT) return;
    int j = idx / KTOT, k = idx % KTOT;
    int c = j >> 2, g = j & 3;
    float v = 0.0f;
    if (k < D_MSG) {
        if (g == 0) v = wih[c * D_MSG + k];
        else if (g == 1) v = wih[(100 + c) * D_MSG + k];
        else if (g == 2) v = wih[(200 + c) * D_MSG + k];
    } else if (k < KREAL) {
        int m = k - D_MSG;
        if (g == 0) v = whh[c * MEM_DIM + m];
        else if (g == 1) v = whh[(100 + c) * MEM_DIM + m];
        else if (g == 3) v = whh[(200 + c) * MEM_DIM + m];
    }
    g_B[idx] = __float2half_rn(v);
}

// ---------------------------------------------------------------------------
// Kernel 1: warp-per-node msg MLP + layernorms. Coalesced msgs via smem.
// ---------------------------------------------------------------------------
__global__ __launch_bounds__(256) void phase1(
    const int* __restrict__ n_id,
    const float* __restrict__ memory,
    const float* __restrict__ msgs,
    const float* __restrict__ w1, const float* __restrict__ b1,
    const float* __restrict__ w2, const float* __restrict__ b2,
    const float* __restrict__ lg, const float* __restrict__ lb,
    const float* __restrict__ lng, const float* __restrict__ lnb,
    int N)
{
    __shared__ float w1s[200], w2s[30];
    __shared__ float b1s[10], b2s[3], lgs[3], lbs[3];
    __shared__ float sv[8][296];
    __shared__ __align__(16) float smsg[8][RAW * TIN];   // 40 KB

    int tid = threadIdx.x;
    int warp = tid >> 5, lane = tid & 31;

    if (tid < 200) w1s[tid] = w1[tid];
    else if (tid < 230) w2s[tid - 200] = w2[tid - 200];
    else if (tid < 240) b1s[tid - 230] = b1[tid - 230];
    else if (tid < 243) b2s[tid - 240] = b2[tid - 240];
    else if (tid < 246) lgs[tid - 243] = lg[tid - 243];
    else if (tid < 249) lbs[tid - 246] = lb[tid - 246];
    __syncthreads();

    int i = blockIdx.x * 8 + warp;
    size_t base = (size_t)i * AK;

    if (i >= N) {
        uint4 z = make_uint4(0, 0, 0, 0);
        uint4* dst = (uint4*)(g_A + base);
        if (lane < 26) { dst[lane] = z; dst[lane + 26] = z; }
        return;
    }
    int row = n_id[i];
    float* svw = sv[warp];

    const float* memrow = memory + (size_t)row * MEM_DIM;
#pragma unroll
    for (int c = lane; c < MEM_DIM; c += 32) svw[c] = memrow[c];

    // ---- coalesced msgs load: 320 float4 chunks, lane+32q pattern ----
    {
        const float4* m4 = (const float4*)(msgs + (size_t)row * (RAW * TIN));
        float4* s4 = (float4*)smsg[warp];
#pragma unroll
        for (int q = 0; q < 10; q++) s4[lane + 32 * q] = __ldg(m4 + lane + 32 * q);
    }
    __syncwarp();

    // each lane reads its 2 rows from smem
    float mr[2][TIN];
#pragma unroll
    for (int rr = 0; rr < 2; rr++) {
        const float4* rp = (const float4*)(smsg[warp] + (2 * lane + rr) * TIN);
#pragma unroll
        for (int q = 0; q < 5; q++) {
            float4 v = rp[q];
            mr[rr][q * 4 + 0] = v.x; mr[rr][q * 4 + 1] = v.y;
            mr[rr][q * 4 + 2] = v.z; mr[rr][q * 4 + 3] = v.w;
        }
    }

    float h0[10], h1[10];
#pragma unroll
    for (int j = 0; j < 10; j++) {
        float s0 = b1s[j], s1 = b1s[j];
#pragma unroll
        for (int t = 0; t < TIN; t++) {
            float w = w1s[j * TIN + t];
            s0 = fmaf(mr[0][t], w, s0);
            s1 = fmaf(mr[1][t], w, s1);
        }
        h0[j] = 0.5f * s0 * (1.0f + erff(s0 * 0.7071067811865476f));
        h1[j] = 0.5f * s1 * (1.0f + erff(s1 * 0.7071067811865476f));
    }
#pragma unroll
    for (int rr = 0; rr < 2; rr++) {
        const float* h = rr ? h1 : h0;
        float y[3];
#pragma unroll
        for (int o = 0; o < 3; o++) {
            float s = b2s[o];
#pragma unroll
            for (int j = 0; j < 10; j++) s = fmaf(h[j], w2s[o * 10 + j], s);
            y[o] = s;
        }
        float mu = (y[0] + y[1] + y[2]) * (1.0f / 3.0f);
        float d0 = y[0] - mu, d1 = y[1] - mu, d2 = y[2] - mu;
        float var = (d0 * d0 + d1 * d1 + d2 * d2) * (1.0f / 3.0f);
        float rs = rsqrtf(var + 1e-5f);
        int r = 2 * lane + rr;
        svw[MEM_DIM + 3 * r + 0] = d0 * rs * lgs[0] + lbs[0];
        svw[MEM_DIM + 3 * r + 1] = d1 * rs * lgs[1] + lbs[1];
        svw[MEM_DIM + 3 * r + 2] = d2 * rs * lgs[2] + lbs[2];
    }
    __syncwarp();

    float s1 = 0.0f, s2 = 0.0f;
#pragma unroll
    for (int k = lane; k < D_MSG; k += 32) { float v = svw[k]; s1 += v; s2 += v * v; }
#pragma unroll
    for (int o = 16; o > 0; o >>= 1) {
        s1 += __shfl_xor_sync(0xFFFFFFFFu, s1, o);
        s2 += __shfl_xor_sync(0xFFFFFFFFu, s2, o);
    }
    float mu = s1 * (1.0f / 292.0f);
    float var = s2 * (1.0f / 292.0f) - mu * mu;
    float rs = rsqrtf(var + 1e-5f);

#pragma unroll
    for (int k = lane; k < D_MSG; k += 32) {
        float v = (svw[k] - mu) * rs * __ldg(lng + k) + __ldg(lnb + k);
        g_A[base + k] = __float2half_rn(v);
    }
#pragma unroll
    for (int c = lane; c < MEM_DIM; c += 32) {
        float v = svw[c];
        g_A[base + D_MSG + c] = __float2half_rn(v);
        g_mem[(size_t)i * MEM_DIM + c] = v;
    }
    if (lane < 24) g_A[base + KREAL + lane] = __float2half_rn(0.0f);
}

// ---------------------------------------------------------------------------
// Kernel 2: fp16 HMMA GEMM + register-fused GRU epilogue. (R12 config +
// last-iteration wait0 drain fix.)
// BM=128 BN=80 BK=32, 256 threads, 8 warps (4x2), 3-stage cp.async pipeline.
// ---------------------------------------------------------------------------
#define BM 128
#define BN 80
#define BK 32
#define LDS 40
#define NKT (KTOT / BK)   // 13
#define A_H (BM * LDS)    // 5120 halves
#define B_H (BN * LDS)    // 3200 halves
#define STG_H (A_H + B_H) // 8320 halves
#define SMEM_GEMM (3 * STG_H * 2)   // 49920 B

__global__ __launch_bounds__(256, 2) void gemm17(float* __restrict__ out, int N) {
    extern __shared__ __align__(16) uint16_t smx[];

    int tid = threadIdx.x;
    int lane = tid & 31, wid = tid >> 5;
    int wm = wid & 3, wn = wid >> 2;            // 4 x 2 warp grid
    int row0 = blockIdx.y * BM;
    int colblk = blockIdx.x;                    // channels [colblk*20, +20)
    int col0 = colblk * BN;

    const uint16_t* gA = (const uint16_t*)g_A;
    const uint16_t* gB = (const uint16_t*)g_B;

    float acc[2][5][4];
#pragma unroll
    for (int mf = 0; mf < 2; mf++)
#pragma unroll
        for (int nf = 0; nf < 5; nf++)
#pragma unroll
            for (int q = 0; q < 4; q++) acc[mf][nf][q] = 0.0f;

    const uint16_t* gsrc[4];
    uint32_t sdst[4];
    bool valid[4];
#pragma unroll
    for (int q = 0; q < 4; q++) {
        int id = tid + q * 256;
        valid[q] = (id < 832);
        if (id < 512) {
            int r = id >> 2, c = id & 3;
            gsrc[q] = gA + (size_t)(row0 + r) * AK + c * 8;
            sdst[q] = r * LDS + c * 8;
        } else if (id < 832) {
            int id2 = id - 512;
            int r = id2 >> 2, c = id2 & 3;
            gsrc[q] = gB + (size_t)(col0 + r) * KTOT + c * 8;
            sdst[q] = A_H + r * LDS + c * 8;
        } else {
            gsrc[q] = gB; sdst[q] = 0;
        }
    }
    uint32_t sbase = smem_u32(smx);

    auto load_stage = [&](int stage, int k0) {
        uint32_t soff = sbase + (uint32_t)(stage * STG_H) * 2;
#pragma unroll
        for (int q = 0; q < 4; q++) {
            if (!valid[q]) continue;
            cp_async16(soff + sdst[q] * 2, gsrc[q] + k0);
        }
        cp_commit();
    };

    load_stage(0, 0);
    load_stage(1, BK);

    for (int kt = 0; kt < NKT; kt++) {
        int buf = kt % 3;
        if (kt + 1 < NKT) cp_wait1(); else cp_wait0();
        __syncthreads();
        if (kt + 2 < NKT) load_stage((kt + 2) % 3, (kt + 2) * BK);

        uint16_t* As = smx + buf * STG_H;
        uint16_t* Bs = As + A_H;
#pragma unroll
        for (int ks = 0; ks < 2; ks++) {
            int k0 = ks * 16;
            uint32_t a[2][4], b[5][2];
#pragma unroll
            for (int mf = 0; mf < 2; mf++) {
                int r = wm * 32 + mf * 16 + (lane & 15);
                int c = k0 + (lane >> 4) * 8;
                ldmx4(a[mf], smem_u32(&As[r * LDS + c]));
            }
#pragma unroll
            for (int pr = 0; pr < 2; pr++) {
                int r = wn * 40 + pr * 16 + (lane & 7) + ((lane >> 4) << 3);
                int c = k0 + ((lane >> 3) & 1) * 8;
                uint32_t bb[4];
                ldmx4(bb, smem_u32(&Bs[r * LDS + c]));
                b[2 * pr][0] = bb[0]; b[2 * pr][1] = bb[1];
                b[2 * pr + 1][0] = bb[2]; b[2 * pr + 1][1] = bb[3];
            }
            {
                int r = wn * 40 + 32 + (lane & 7);
                int c = k0 + ((lane >> 3) & 1) * 8;
                ldmx2(b[4], smem_u32(&Bs[r * LDS + c]));
            }
#pragma unroll
            for (int mf = 0; mf < 2; mf++)
#pragma unroll
                for (int nf = 0; nf < 5; nf++)
                    mma16816(acc[mf][nf], a[mf], b[nf]);
        }
    }

    // Register-fused GRU epilogue.
#pragma unroll
    for (int mf = 0; mf < 2; mf++) {
        int r0i = row0 + wm * 32 + mf * 16 + (lane >> 2);
#pragma unroll
        for (int nf = 0; nf < 5; nf++) {
            float n0 = __shfl_xor_sync(0xFFFFFFFFu, acc[mf][nf][0], 1);
            float n1 = __shfl_xor_sync(0xFFFFFFFFu, acc[mf][nf][1], 1);
            float n2 = __shfl_xor_sync(0xFFFFFFFFu, acc[mf][nf][2], 1);
            float n3 = __shfl_xor_sync(0xFFFFFFFFu, acc[mf][nf][3], 1);
            if (!(lane & 1)) {
                int ch = colblk * 20 + wn * 10 + nf * 2 + ((lane & 3) >> 1);
                if (ch < MEM_DIM) {
                    if (r0i < N) {
                        float rr = 1.0f / (1.0f + expf(-acc[mf][nf][0]));
                        float zz = 1.0f / (1.0f + expf(-acc[mf][nf][1]));
                        float nn = tanhf(fmaf(rr, n1, n0));
                        float m = g_mem[(size_t)r0i * MEM_DIM + ch];
                        out[(size_t)r0i * MEM_DIM + ch] = (1.0f - zz) * nn + zz * m;
                    }
                    int r1i = r0i + 8;
                    if (r1i < N) {
                        float rr = 1.0f / (1.0f + expf(-acc[mf][nf][2]));
                        float zz = 1.0f / (1.0f + expf(-acc[mf][nf][3]));
                        float nn = tanhf(fmaf(rr, n3, n2));
                        float m = g_mem[(size_t)r1i * MEM_DIM + ch];
                        out[(size_t)r1i * MEM_DIM + ch] = (1.0f - zz) * nn + zz * m;
                    }
                }
            }
        }
    }
}

// ---------------------------------------------------------------------------
extern "C" void kernel_launch(void* const* d_in, const int* in_sizes, int n_in,
                              void* d_out, int out_size) {
    const int*   n_id   = (const int*)d_in[0];
    const float* memory = (const float*)d_in[1];
    const float* msgs   = (const float*)d_in[2];
    const float* w1     = (const float*)d_in[3];
    const float* b1     = (const float*)d_in[4];
    const float* w2     = (const float*)d_in[5];
    const float* b2     = (const float*)d_in[6];
    const float* lg     = (const float*)d_in[7];
    const float* lb     = (const float*)d_in[8];
    const float* lng    = (const float*)d_in[9];
    const float* lnb    = (const float*)d_in[10];
    const float* wih    = (const float*)d_in[11];
    const float* whh    = (const float*)d_in[12];
    float* out = (float*)d_out;

    int N = in_sizes[0];
    if (N > N_MAXN) N = N_MAXN;

    cudaFuncSetAttribute(gemm17, cudaFuncAttributeMaxDynamicSharedMemorySize, SMEM_GEMM);

    buildB<<<(JB * KTOT + 255) / 256, 256>>>(wih, whh);
    phase1<<<NPAD / 8, 256>>>(n_id, memory, msgs, w1, b1, w2, b2, lg, lb, lng, lnb, N);
    dim3 grid(5, NPAD / BM);   // col-block fast -> A shared in L2
    gemm17<<<grid, 256, SMEM_GEMM>>>(out, N);
}